// round 7
// baseline (speedup 1.0000x reference)
#include <cuda_runtime.h>
#include <cstdint>

// 2-bit quantized embedding lookup — warp-per-token layout.
// ids: [262144] (int32 OR int64, runtime-detected), bit_arr: [3.2M] int32,
// codebook: [4] float. Token's 128 codes = 8 aligned int32 words at bit_arr[tok*8].
//
// One warp per token: lane l writes float4 for dims 4l..4l+3 at out+tok*512+l*16.
// The warp's single STG.128 covers 512B = 4 FULL 128B lines (minimum store
// wavefronts). Lane l reads word l>>2 (4-lane broadcast, one 32B segment/warp)
// and extracts codes from byte (l&3) at bit offsets {0,2,4,6}.

__device__ int g_id_stride;   // 1 if ids are int32, 2 if ids are int64 (low word)

// For int64 ids (nonneg < 2^31) every odd 32-bit word is zero; for int32 the
// odd words are random ids (all-zero prob ~ (1/400000)^512 ≈ 0). Deterministic.
__global__ void detect_id_stride_kernel(const unsigned* __restrict__ w32)
{
    unsigned acc = 0;
    #pragma unroll 4
    for (int i = threadIdx.x; i < 512; i += 32)
        acc |= w32[2 * i + 1];
    unsigned any = __any_sync(0xffffffffu, acc != 0u);
    if (threadIdx.x == 0)
        g_id_stride = any ? 1 : 2;
}

__global__ void __launch_bounds__(256) embed2b_kernel(
    const unsigned* __restrict__ idw,   // ids viewed as 32-bit words
    const unsigned* __restrict__ bits,
    const float*    __restrict__ cb,
    float4*         __restrict__ out,
    int n_tokens)
{
    int gt    = blockIdx.x * blockDim.x + threadIdx.x;
    int token = gt >> 5;
    int lane  = gt & 31;
    if (token >= n_tokens) return;

    int stride = g_id_stride;            // uniform, L1 hit

    float c0 = __ldg(cb + 0);
    float c1 = __ldg(cb + 1);
    float c2 = __ldg(cb + 2);
    float c3 = __ldg(cb + 3);

    // little-endian: low 32-bit word holds the full id in either layout
    unsigned tok = __ldg(idw + (size_t)token * stride);   // 32-lane broadcast
    unsigned w   = __ldg(bits + tok * 8u + (lane >> 2));  // 4-lane broadcast, 32B/warp

    unsigned b = w >> ((lane & 3) * 8);  // this lane's byte: 4 codes

    float4 v;
    {
        unsigned code = b & 3u;
        float a = (code & 1u) ? c1 : c0;
        float d = (code & 1u) ? c3 : c2;
        v.x = (code & 2u) ? d : a;
    }
    {
        unsigned code = (b >> 2) & 3u;
        float a = (code & 1u) ? c1 : c0;
        float d = (code & 1u) ? c3 : c2;
        v.y = (code & 2u) ? d : a;
    }
    {
        unsigned code = (b >> 4) & 3u;
        float a = (code & 1u) ? c1 : c0;
        float d = (code & 1u) ? c3 : c2;
        v.z = (code & 2u) ? d : a;
    }
    {
        unsigned code = (b >> 6) & 3u;
        float a = (code & 1u) ? c1 : c0;
        float d = (code & 1u) ? c3 : c2;
        v.w = (code & 2u) ? d : a;
    }

    // warp writes token*512 .. +512: 4 full 128B lines, perfectly coalesced
    out[(size_t)token * 32 + lane] = v;
}

extern "C" void kernel_launch(void* const* d_in, const int* in_sizes, int n_in,
                              void* d_out, int out_size)
{
    const unsigned* idw  = (const unsigned*)d_in[0];  // ids (int32 or int64)
    const unsigned* bits = (const unsigned*)d_in[1];  // packed 2-bit codes
    const float*    cb   = (const float*)d_in[2];     // 4-entry codebook
    float*          out  = (float*)d_out;             // [N, 128] fp32

    int n_tokens = in_sizes[0];                        // 64*4096 = 262144

    detect_id_stride_kernel<<<1, 32>>>(idw);

    long long total_threads = (long long)n_tokens * 32;
    int block = 256;
    int grid = (int)((total_threads + block - 1) / block);
    embed2b_kernel<<<grid, block>>>(idw, bits, cb, (float4*)out, n_tokens);
}

// round 9
// speedup vs baseline: 1.6359x; 1.6359x over previous
#include <cuda_runtime.h>
#include <cstdint>

// 2-bit quantized embedding lookup — warp processes 8 tokens (MLP=8).
// ids: [262144] (int32 OR int64, runtime-detected), bit_arr: [3.2M] int32,
// codebook: [4] float. Token's 128 codes = 8 aligned int32 words at bit_arr[tok*8].
//
// Per warp: lane l loads id[wbase+(l&7)]; shfl(width=8) broadcasts the 8 ids;
// 8 independent bit-word loads issue back to back (hides L2/DRAM latency);
// then 8 decode+store rounds, each a fully coalesced 512B STG.128 burst
// (4 full 128B lines). Lane l owns dims 4l..4l+3 of each token.

__device__ int g_id_stride;   // 1 if ids are int32, 2 if ids are int64 (low word)

// For int64 ids (nonneg < 2^31) every odd 32-bit word is zero; for int32 the
// odd words are random ids (all-zero prob ~ (1/4e5)^512 ≈ 0). Deterministic.
__global__ void detect_id_stride_kernel(const unsigned* __restrict__ w32)
{
    __shared__ int any_nonzero;
    if (threadIdx.x == 0) any_nonzero = 0;
    __syncthreads();
    unsigned acc = w32[2 * threadIdx.x + 1] | w32[2 * (threadIdx.x + 256) + 1];
    if (acc) atomicOr(&any_nonzero, 1);
    __syncthreads();
    if (threadIdx.x == 0)
        g_id_stride = any_nonzero ? 1 : 2;   // nonzero odd words => int32
}

#define TPW 8   // tokens per warp

__device__ __forceinline__ float4 decode16(unsigned b,
                                           float c0, float c1, float c2, float c3)
{
    float4 v;
    {
        unsigned code = b & 3u;
        float a = (code & 1u) ? c1 : c0;
        float d = (code & 1u) ? c3 : c2;
        v.x = (code & 2u) ? d : a;
    }
    {
        unsigned code = (b >> 2) & 3u;
        float a = (code & 1u) ? c1 : c0;
        float d = (code & 1u) ? c3 : c2;
        v.y = (code & 2u) ? d : a;
    }
    {
        unsigned code = (b >> 4) & 3u;
        float a = (code & 1u) ? c1 : c0;
        float d = (code & 1u) ? c3 : c2;
        v.z = (code & 2u) ? d : a;
    }
    {
        unsigned code = (b >> 6) & 3u;
        float a = (code & 1u) ? c1 : c0;
        float d = (code & 1u) ? c3 : c2;
        v.w = (code & 2u) ? d : a;
    }
    return v;
}

__global__ void __launch_bounds__(256) embed2b_kernel(
    const unsigned* __restrict__ idw,   // ids viewed as 32-bit words
    const unsigned* __restrict__ bits,
    const float*    __restrict__ cb,
    float4*         __restrict__ out,
    int n_tokens)
{
    int gt    = blockIdx.x * blockDim.x + threadIdx.x;
    int lane  = threadIdx.x & 31;
    int wbase = (gt >> 5) * TPW;        // first token of this warp
    if (wbase >= n_tokens) return;

    int stride = g_id_stride;           // uniform, L1 hit

    float c0 = __ldg(cb + 0);
    float c1 = __ldg(cb + 1);
    float c2 = __ldg(cb + 2);
    float c3 = __ldg(cb + 3);

    int wsel = lane >> 2;               // which packed word this lane needs
    int bsh  = (lane & 3) * 8;          // byte shift within that word

    if (wbase + TPW <= n_tokens) {
        // ---- fast path: full group of 8 tokens ----
        // lane l holds id of token wbase + (l&7); low word = full value (LE)
        unsigned myid = __ldg(idw + (size_t)(wbase + (lane & (TPW - 1))) * stride);

        unsigned toks[TPW];
        #pragma unroll
        for (int t = 0; t < TPW; t++)
            toks[t] = __shfl_sync(0xffffffffu, myid, t, TPW);

        unsigned w[TPW];
        #pragma unroll
        for (int t = 0; t < TPW; t++)           // 8 independent loads, MLP=8
            w[t] = __ldg(bits + toks[t] * 8u + wsel);

        #pragma unroll
        for (int t = 0; t < TPW; t++) {
            float4 v = decode16(w[t] >> bsh, c0, c1, c2, c3);
            out[(size_t)(wbase + t) * 32 + lane] = v;   // 4 full 128B lines
        }
    } else {
        // ---- tail: per-token ----
        for (int t = 0; t < TPW && wbase + t < n_tokens; t++) {
            unsigned tok = __ldg(idw + (size_t)(wbase + t) * stride);
            unsigned w   = __ldg(bits + tok * 8u + wsel);
            float4 v = decode16(w >> bsh, c0, c1, c2, c3);
            out[(size_t)(wbase + t) * 32 + lane] = v;
        }
    }
}

extern "C" void kernel_launch(void* const* d_in, const int* in_sizes, int n_in,
                              void* d_out, int out_size)
{
    const unsigned* idw  = (const unsigned*)d_in[0];  // ids (int32 or int64)
    const unsigned* bits = (const unsigned*)d_in[1];  // packed 2-bit codes
    const float*    cb   = (const float*)d_in[2];     // 4-entry codebook
    float*          out  = (float*)d_out;             // [N, 128] fp32

    int n_tokens = in_sizes[0];                        // 64*4096 = 262144

    detect_id_stride_kernel<<<1, 256>>>(idw);

    int warps  = (n_tokens + TPW - 1) / TPW;
    long long total_threads = (long long)warps * 32;
    int block = 256;
    int grid = (int)((total_threads + block - 1) / block);
    embed2b_kernel<<<grid, block>>>(idw, bits, cb, (float4*)out, n_tokens);
}